// round 11
// baseline (speedup 1.0000x reference)
#include <cuda_runtime.h>
#include <stdint.h>
#include <stddef.h>

#define BB 128
#define NN 2048
#define EE 16384

// scratch (static device globals; no runtime allocation)
__device__ float  g_dis[BB * NN];
__device__ int    g_n[BB];
__device__ int    g_rowptr[BB * (NN + 1)];
__device__ float2 g_csr[(size_t)BB * EE];     // .x = src (int bits), .y = norm
__device__ float  g_h[(size_t)BB * NN * 64];  // h1 (layer-1 output)
__device__ float  g_pool[BB * 64];            // pooled partial sums
__device__ int    g_cnt[BB];                  // per-batch tile-arrival counters

typedef unsigned long long ull;

__device__ __forceinline__ void fma2(ull& d, ull a, ull b) {
    asm("fma.rn.f32x2 %0, %1, %2, %0;" : "+l"(d) : "l"(a), "l"(b));
}
__device__ __forceinline__ ull pack2(float x, float y) {
    ull r; asm("mov.b64 %0, {%1, %2};" : "=l"(r) : "f"(x), "f"(y)); return r;
}
__device__ __forceinline__ float2 unpack2(ull v) {
    float2 u; asm("mov.b64 {%0, %1}, %2;" : "=f"(u.x), "=f"(u.y) : "l"(v)); return u;
}

// node_mask dtype hedge: rows are prefix masks with n >= 1024, so element 1 is
// always "true". If stored as 1-byte bool, byte[1]==1. If stored as int32 or
// float32 (4-byte elems), byte[1]==0.
__device__ __forceinline__ bool mask_is_wide(const unsigned char* m) {
    return m[1] == 0;
}
__device__ __forceinline__ bool mask_at(const unsigned char* m, bool wide, size_t idx) {
    return wide ? (((const int*)m)[idx] != 0) : (m[idx] != 0);
}

// ---------------------------------------------------------------------------
// K0: per-batch degree, dis = rsqrt(deg), CSR build (valid edges only, with
// per-edge norm precomputed), node count n, zero pool accumulators + counters.
// ---------------------------------------------------------------------------
__global__ __launch_bounds__(512) void k_prep(const int* __restrict__ ei,
                                              const unsigned char* __restrict__ msk) {
    __shared__ int   sdeg[NN];
    __shared__ float sdis[NN];
    __shared__ int   srow[NN];
    __shared__ int   scur[NN];
    __shared__ int   ssum[512];
    __shared__ unsigned char smask[NN];
    __shared__ int   s_n;

    const int b = blockIdx.x;
    const int t = threadIdx.x;
    const bool wide = mask_is_wide(msk);
    const size_t mb = (size_t)b * NN;
    const int* src = ei + (size_t)b * 2 * EE;
    const int* dst = src + EE;
    const int4* src4 = (const int4*)src;
    const int4* dst4 = (const int4*)dst;

    if (t == 0) { s_n = 0; g_cnt[b] = 0; }
    if (t < 64) g_pool[b * 64 + t] = 0.f;
    int cnt = 0;
    for (int i = t; i < NN; i += 512) {
        sdeg[i] = 0;
        unsigned char m = mask_at(msk, wide, mb + i) ? 1 : 0;
        smask[i] = m;
        cnt += m;
    }
    __syncthreads();
    atomicAdd(&s_n, cnt);

    // degree of valid edges (4 edges per thread-iter)
    for (int e4 = t; e4 < EE / 4; e4 += 512) {
        int4 s = src4[e4], d = dst4[e4];
        if (smask[s.x] & smask[d.x]) atomicAdd(&sdeg[d.x], 1);
        if (smask[s.y] & smask[d.y]) atomicAdd(&sdeg[d.y], 1);
        if (smask[s.z] & smask[d.z]) atomicAdd(&sdeg[d.z], 1);
        if (smask[s.w] & smask[d.w]) atomicAdd(&sdeg[d.w], 1);
    }
    __syncthreads();

    // dis = rsqrt(deg + self)
    for (int i = t; i < NN; i += 512) {
        float dg = (float)sdeg[i] + (float)smask[i];
        sdis[i] = (dg > 0.f) ? rsqrtf(dg) : 0.f;
        g_dis[mb + i] = sdis[i];
    }
    __syncthreads();

    // exclusive scan of sdeg -> srow (each thread owns 4 consecutive entries)
    {
        int base = t * 4;
        int a0 = sdeg[base], a1 = sdeg[base + 1], a2 = sdeg[base + 2], a3 = sdeg[base + 3];
        int tot = a0 + a1 + a2 + a3;
        ssum[t] = tot;
        __syncthreads();
#pragma unroll
        for (int off = 1; off < 512; off <<= 1) {
            int v = ssum[t];
            int u = (t >= off) ? ssum[t - off] : 0;
            __syncthreads();
            ssum[t] = v + u;
            __syncthreads();
        }
        int excl = ssum[t] - tot;
        srow[base]     = excl;
        srow[base + 1] = excl + a0;
        srow[base + 2] = excl + a0 + a1;
        srow[base + 3] = excl + a0 + a1 + a2;
        scur[base]     = srow[base];
        scur[base + 1] = srow[base + 1];
        scur[base + 2] = srow[base + 2];
        scur[base + 3] = srow[base + 3];
    }
    __syncthreads();

    // write rowptr
    int* rp = g_rowptr + (size_t)b * (NN + 1);
    for (int i = t; i < NN; i += 512) rp[i] = srow[i];
    if (t == 511) {
        rp[NN] = ssum[511];
        g_n[b] = s_n;
    }
    __syncthreads();

    // scatter valid edges with norm
    float2* csr = g_csr + (size_t)b * EE;
    for (int e4 = t; e4 < EE / 4; e4 += 512) {
        int4 s = src4[e4], d = dst4[e4];
        int ss[4] = {s.x, s.y, s.z, s.w};
        int dd[4] = {d.x, d.y, d.z, d.w};
#pragma unroll
        for (int k = 0; k < 4; k++) {
            if (smask[ss[k]] & smask[dd[k]]) {
                int pos = atomicAdd(&scur[dd[k]], 1);
                float2 v;
                v.x = __int_as_float(ss[k]);
                v.y = sdis[ss[k]] * sdis[dd[k]];
                csr[pos] = v;
            }
        }
    }
}

// ---------------------------------------------------------------------------
// K1: fused GCN layer. One CTA per (batch, 128-node tile), 256 threads.
//   Phase 1: CSR gather-aggregate z rows into smem (no atomics).
//   Phase 2: 128xF @ Fx64 GEMM from smem via packed fma.rn.f32x2.
//   Epilogue: F==32 -> write h1;  F==64 -> pool sums; last tile runs MLP head.
// ---------------------------------------------------------------------------
template <int F>
__global__ __launch_bounds__(256) void k_layer(const float* __restrict__ xin,
                                               const float* __restrict__ W,
                                               const float* __restrict__ bias,
                                               const unsigned char* __restrict__ msk,
                                               const float* __restrict__ aW1,
                                               const float* __restrict__ ab1,
                                               const float* __restrict__ aW2,
                                               const float* __restrict__ ab2,
                                               float* __restrict__ out) {
    constexpr int SZ = F + 4;  // padded row stride (multiple of 4 for float4)
    extern __shared__ float sm[];
    float* sz = sm;              // 128 * SZ
    float* sW = sz + 128 * SZ;   // F * 64
    float* sb = sW + F * 64;     // 64
    float* sp = sb + 64;         // 64 (layer-2 pool partials)
    __shared__ int s_last;

    const int t = threadIdx.x;
    const int b = blockIdx.x >> 4;               // 16 tiles per batch
    const size_t gnode0 = (size_t)blockIdx.x * 128;
    const int lnode0 = (blockIdx.x & 15) * 128;  // first node within batch

    for (int i = t; i < F * 64; i += 256) sW[i] = W[i];
    if (t < 64) {
        sb[t] = bias[t];
        if (F == 64) sp[t] = 0.f;
    }

    const float* hb = (F == 32) ? xin + (size_t)b * NN * 32
                                : (const float*)g_h + (size_t)b * NN * 64;
    const float2* csr = g_csr + (size_t)b * EE;
    const int* rp = g_rowptr + (size_t)b * (NN + 1);
    const float* dis = g_dis + (size_t)b * NN;

    const int warp = t >> 5, lane = t & 31;

    // ---- Phase 1: gather-aggregate ----
    if (F == 64) {
        const int g = lane >> 4, cl = lane & 15;  // 2 groups x 16 lanes x float4
#pragma unroll 1
        for (int k = 0; k < 16; k++) {
            const int li = warp * 16 + k;
            const int i = lnode0 + li;
            const int r0 = rp[i], r1 = rp[i + 1];
            float4 acc = make_float4(0.f, 0.f, 0.f, 0.f);
            if (g == 0) {
                float di = dis[i];
                float s = di * di;
                float4 hv = *(const float4*)(hb + (size_t)i * 64 + cl * 4);
                acc.x = s * hv.x; acc.y = s * hv.y; acc.z = s * hv.z; acc.w = s * hv.w;
            }
            int e = r0 + g;
            for (; e + 2 < r1; e += 4) {  // 2 edges in flight per group
                float2 cA = csr[e], cB = csr[e + 2];
                const float4 gA = *(const float4*)(hb + (size_t)__float_as_int(cA.x) * 64 + cl * 4);
                const float4 gB = *(const float4*)(hb + (size_t)__float_as_int(cB.x) * 64 + cl * 4);
                acc.x = fmaf(cA.y, gA.x, acc.x); acc.y = fmaf(cA.y, gA.y, acc.y);
                acc.z = fmaf(cA.y, gA.z, acc.z); acc.w = fmaf(cA.y, gA.w, acc.w);
                acc.x = fmaf(cB.y, gB.x, acc.x); acc.y = fmaf(cB.y, gB.y, acc.y);
                acc.z = fmaf(cB.y, gB.z, acc.z); acc.w = fmaf(cB.y, gB.w, acc.w);
            }
            for (; e < r1; e += 2) {
                float2 c = csr[e];
                const float4 gv = *(const float4*)(hb + (size_t)__float_as_int(c.x) * 64 + cl * 4);
                acc.x = fmaf(c.y, gv.x, acc.x); acc.y = fmaf(c.y, gv.y, acc.y);
                acc.z = fmaf(c.y, gv.z, acc.z); acc.w = fmaf(c.y, gv.w, acc.w);
            }
            acc.x += __shfl_xor_sync(0xffffffffu, acc.x, 16);
            acc.y += __shfl_xor_sync(0xffffffffu, acc.y, 16);
            acc.z += __shfl_xor_sync(0xffffffffu, acc.z, 16);
            acc.w += __shfl_xor_sync(0xffffffffu, acc.w, 16);
            if (g == 0) *(float4*)(sz + li * SZ + cl * 4) = acc;
        }
    } else {
        const int g = lane >> 3, cl = lane & 7;  // 4 groups x 8 lanes x float4
#pragma unroll 1
        for (int k = 0; k < 16; k++) {
            const int li = warp * 16 + k;
            const int i = lnode0 + li;
            const int r0 = rp[i], r1 = rp[i + 1];
            float4 acc = make_float4(0.f, 0.f, 0.f, 0.f);
            if (g == 0) {
                float di = dis[i];
                float s = di * di;
                float4 hv = *(const float4*)(hb + (size_t)i * 32 + cl * 4);
                acc.x = s * hv.x; acc.y = s * hv.y; acc.z = s * hv.z; acc.w = s * hv.w;
            }
            int e = r0 + g;
            for (; e + 4 < r1; e += 8) {  // 2 edges in flight per group
                float2 cA = csr[e], cB = csr[e + 4];
                const float4 gA = *(const float4*)(hb + (size_t)__float_as_int(cA.x) * 32 + cl * 4);
                const float4 gB = *(const float4*)(hb + (size_t)__float_as_int(cB.x) * 32 + cl * 4);
                acc.x = fmaf(cA.y, gA.x, acc.x); acc.y = fmaf(cA.y, gA.y, acc.y);
                acc.z = fmaf(cA.y, gA.z, acc.z); acc.w = fmaf(cA.y, gA.w, acc.w);
                acc.x = fmaf(cB.y, gB.x, acc.x); acc.y = fmaf(cB.y, gB.y, acc.y);
                acc.z = fmaf(cB.y, gB.z, acc.z); acc.w = fmaf(cB.y, gB.w, acc.w);
            }
            for (; e < r1; e += 4) {
                float2 c = csr[e];
                const float4 gv = *(const float4*)(hb + (size_t)__float_as_int(c.x) * 32 + cl * 4);
                acc.x = fmaf(c.y, gv.x, acc.x); acc.y = fmaf(c.y, gv.y, acc.y);
                acc.z = fmaf(c.y, gv.z, acc.z); acc.w = fmaf(c.y, gv.w, acc.w);
            }
            acc.x += __shfl_xor_sync(0xffffffffu, acc.x, 8);
            acc.y += __shfl_xor_sync(0xffffffffu, acc.y, 8);
            acc.z += __shfl_xor_sync(0xffffffffu, acc.z, 8);
            acc.w += __shfl_xor_sync(0xffffffffu, acc.w, 8);
            acc.x += __shfl_xor_sync(0xffffffffu, acc.x, 16);
            acc.y += __shfl_xor_sync(0xffffffffu, acc.y, 16);
            acc.z += __shfl_xor_sync(0xffffffffu, acc.z, 16);
            acc.w += __shfl_xor_sync(0xffffffffu, acc.w, 16);
            if (g == 0) *(float4*)(sz + li * SZ + cl * 4) = acc;
        }
    }
    __syncthreads();

    // ---- Phase 2: GEMM via packed fma.rn.f32x2 (2 nodes x 16 channels/thread) ----
    const int cg = t & 3;     // channel group (16 ch = 8 packed pairs)
    const int ng = t >> 2;    // node slot 0..63 (rows ng and ng+64)
    const bool wide = mask_is_wide(msk);

    ull acc0[8], acc1[8];
#pragma unroll
    for (int j = 0; j < 8; j++) { acc0[j] = 0ull; acc1[j] = 0ull; }

    const float* zr0p = sz + ng * SZ;
    const float* zr1p = sz + (ng + 64) * SZ;
    for (int f = 0; f < F; f += 4) {
        float4 z0 = *(const float4*)(zr0p + f);
        float4 z1 = *(const float4*)(zr1p + f);
        float za0[4] = {z0.x, z0.y, z0.z, z0.w};
        float za1[4] = {z1.x, z1.y, z1.z, z1.w};
#pragma unroll
        for (int ff = 0; ff < 4; ff++) {
            ull zp0 = pack2(za0[ff], za0[ff]);
            ull zp1 = pack2(za1[ff], za1[ff]);
            const ulonglong2* wp = (const ulonglong2*)(sW + (f + ff) * 64 + cg * 16);
            ulonglong2 wA = wp[0], wB = wp[1], wC = wp[2], wD = wp[3];
            fma2(acc0[0], zp0, wA.x); fma2(acc0[1], zp0, wA.y);
            fma2(acc0[2], zp0, wB.x); fma2(acc0[3], zp0, wB.y);
            fma2(acc0[4], zp0, wC.x); fma2(acc0[5], zp0, wC.y);
            fma2(acc0[6], zp0, wD.x); fma2(acc0[7], zp0, wD.y);
            fma2(acc1[0], zp1, wA.x); fma2(acc1[1], zp1, wA.y);
            fma2(acc1[2], zp1, wB.x); fma2(acc1[3], zp1, wB.y);
            fma2(acc1[4], zp1, wC.x); fma2(acc1[5], zp1, wC.y);
            fma2(acc1[6], zp1, wD.x); fma2(acc1[7], zp1, wD.y);
        }
    }

    // unpack accumulators to scalar channel values
    float oa[2][16];
#pragma unroll
    for (int j = 0; j < 8; j++) {
        float2 u0 = unpack2(acc0[j]);
        float2 u1 = unpack2(acc1[j]);
        oa[0][2 * j] = u0.x; oa[0][2 * j + 1] = u0.y;
        oa[1][2 * j] = u1.x; oa[1][2 * j + 1] = u1.y;
    }

    // ---- Epilogue ----
    if (F == 32) {
        // layer 1: h1 = relu((z@W1 + b1) * mask) -> gmem
#pragma unroll
        for (int k = 0; k < 2; k++) {
            size_t gn = gnode0 + ng + 64 * k;
            float m = mask_at(msk, wide, gn) ? 1.f : 0.f;
            float* outp = g_h + gn * 64 + cg * 16;
#pragma unroll
            for (int q = 0; q < 4; q++) {
                float4 o;
                o.x = fmaxf((oa[k][q * 4 + 0] + sb[cg * 16 + q * 4 + 0]) * m, 0.f);
                o.y = fmaxf((oa[k][q * 4 + 1] + sb[cg * 16 + q * 4 + 1]) * m, 0.f);
                o.z = fmaxf((oa[k][q * 4 + 2] + sb[cg * 16 + q * 4 + 2]) * m, 0.f);
                o.w = fmaxf((oa[k][q * 4 + 3] + sb[cg * 16 + q * 4 + 3]) * m, 0.f);
                ((float4*)outp)[q] = o;
            }
        }
    } else {
        // layer 2: h2 feeds only pooling -> accumulate sum over nodes
        float ps[16];
#pragma unroll
        for (int j = 0; j < 16; j++) ps[j] = 0.f;
#pragma unroll
        for (int k = 0; k < 2; k++) {
            size_t gn = gnode0 + ng + 64 * k;
            float m = mask_at(msk, wide, gn) ? 1.f : 0.f;
#pragma unroll
            for (int j = 0; j < 16; j++)
                ps[j] += fmaxf((oa[k][j] + sb[cg * 16 + j]) * m, 0.f);
        }
        // butterfly over node-group lanes (bits 2..4) — all lanes share cg
#pragma unroll
        for (int j = 0; j < 16; j++) {
            float v = ps[j];
            v += __shfl_xor_sync(0xffffffffu, v, 4);
            v += __shfl_xor_sync(0xffffffffu, v, 8);
            v += __shfl_xor_sync(0xffffffffu, v, 16);
            ps[j] = v;
        }
        if (lane < 4) {  // lane == cg for these lanes
#pragma unroll
            for (int j = 0; j < 16; j++) atomicAdd(&sp[lane * 16 + j], ps[j]);
        }
        __syncthreads();
        if (t < 64) atomicAdd(&g_pool[b * 64 + t], sp[t]);

        // ---- fused MLP head: last-arriving tile of this batch finishes it ----
        __threadfence();
        if (t == 0) s_last = (atomicAdd(&g_cnt[b], 1) == 15) ? 1 : 0;
        __syncthreads();
        if (s_last) {
            __threadfence();  // acquire: all tiles' pool writes visible
            float* pooled = sz;       // reuse smem
            float* hid = sz + 64;
            if (t < 64) {
                int n = g_n[b];
                if (n < 1) n = 1;
                pooled[t] = g_pool[b * 64 + t] / (float)n;
            }
            __syncthreads();
            if (t < 64) {
                float a = ab1[t];
#pragma unroll
                for (int f = 0; f < 64; f++) a = fmaf(pooled[f], aW1[f * 64 + t], a);
                hid[t] = fmaxf(a, 0.f);
            }
            __syncthreads();
            if (t < 16) {
                float a = ab2[t];
#pragma unroll
                for (int f = 0; f < 64; f++) a = fmaf(hid[f], aW2[f * 16 + t], a);
                out[b * 16 + t] = a;
            }
        }
    }
}

// ---------------------------------------------------------------------------
extern "C" void kernel_launch(void* const* d_in, const int* in_sizes, int n_in,
                              void* d_out, int out_size) {
    const float*         x   = (const float*)d_in[0];
    const int*           ei  = (const int*)d_in[1];
    const unsigned char* msk = (const unsigned char*)d_in[2];
    const float* W1  = (const float*)d_in[3];
    const float* b1  = (const float*)d_in[4];
    const float* W2  = (const float*)d_in[5];
    const float* b2  = (const float*)d_in[6];
    const float* aW1 = (const float*)d_in[7];
    const float* ab1 = (const float*)d_in[8];
    const float* aW2 = (const float*)d_in[9];
    const float* ab2 = (const float*)d_in[10];
    float* out = (float*)d_out;

    const int sm32 = (128 * 36 + 32 * 64 + 64 + 64) * 4;  // ~26.5 KB
    const int sm64 = (128 * 68 + 64 * 64 + 64 + 64) * 4;  // ~50.5 KB
    cudaFuncSetAttribute(k_layer<32>, cudaFuncAttributeMaxDynamicSharedMemorySize, sm32);
    cudaFuncSetAttribute(k_layer<64>, cudaFuncAttributeMaxDynamicSharedMemorySize, sm64);

    // prep: degrees, dis, CSR with per-edge norm (invalid edges dropped)
    k_prep<<<BB, 512>>>(ei, msk);
    // layer 1 fused: gather(x) -> GEMM(W1) -> h1
    k_layer<32><<<(BB * NN) / 128, 256, sm32>>>(x, W1, b1, msk, aW1, ab1, aW2, ab2, out);
    // layer 2 fused: gather(h1) -> GEMM(W2) -> pool -> MLP head (last tile)
    k_layer<64><<<(BB * NN) / 128, 256, sm64>>>(x, W2, b2, msk, aW1, ab1, aW2, ab2, out);
}

// round 12
// speedup vs baseline: 1.9078x; 1.9078x over previous
#include <cuda_runtime.h>
#include <stdint.h>
#include <stddef.h>

#define BB 128
#define NN 2048
#define EE 16384

// scratch (static device globals; no runtime allocation)
__device__ float  g_dis[BB * NN];
__device__ int    g_n[BB];
__device__ int    g_rowptr[BB * (NN + 1)];
__device__ float2 g_csr[(size_t)BB * EE];     // .x = src (int bits), .y = norm
__device__ float  g_h[(size_t)BB * NN * 64];  // h1 (layer-1 output)
__device__ float  g_pool[BB * 64];            // pooled partial sums

// node_mask dtype hedge: rows are prefix masks with n >= 1024, so element 1 is
// always "true". If stored as 1-byte bool, byte[1]==1. If stored as int32 or
// float32 (4-byte elems), byte[1]==0.
__device__ __forceinline__ bool mask_is_wide(const unsigned char* m) {
    return m[1] == 0;
}
__device__ __forceinline__ bool mask_at(const unsigned char* m, bool wide, size_t idx) {
    return wide ? (((const int*)m)[idx] != 0) : (m[idx] != 0);
}

// ---------------------------------------------------------------------------
// K0: per-batch degree, dis = rsqrt(deg), CSR build (valid edges only, with
// per-edge norm precomputed), node count n, zero pool accumulators.
// One 512-thread CTA per batch. Edge lists read as int4.
// ---------------------------------------------------------------------------
__global__ __launch_bounds__(512) void k_prep(const int* __restrict__ ei,
                                              const unsigned char* __restrict__ msk) {
    __shared__ int   sdeg[NN];
    __shared__ float sdis[NN];
    __shared__ int   srow[NN];
    __shared__ int   scur[NN];
    __shared__ int   ssum[512];
    __shared__ unsigned char smask[NN];
    __shared__ int   s_n;

    const int b = blockIdx.x;
    const int t = threadIdx.x;
    const bool wide = mask_is_wide(msk);
    const size_t mb = (size_t)b * NN;
    const int* src = ei + (size_t)b * 2 * EE;
    const int* dst = src + EE;
    const int4* src4 = (const int4*)src;
    const int4* dst4 = (const int4*)dst;

    if (t == 0) s_n = 0;
    if (t < 64) g_pool[b * 64 + t] = 0.f;
    int cnt = 0;
    for (int i = t; i < NN; i += 512) {
        sdeg[i] = 0;
        unsigned char m = mask_at(msk, wide, mb + i) ? 1 : 0;
        smask[i] = m;
        cnt += m;
    }
    __syncthreads();
    atomicAdd(&s_n, cnt);

    // degree of valid edges (4 edges per thread-iter)
    for (int e4 = t; e4 < EE / 4; e4 += 512) {
        int4 s = src4[e4], d = dst4[e4];
        if (smask[s.x] & smask[d.x]) atomicAdd(&sdeg[d.x], 1);
        if (smask[s.y] & smask[d.y]) atomicAdd(&sdeg[d.y], 1);
        if (smask[s.z] & smask[d.z]) atomicAdd(&sdeg[d.z], 1);
        if (smask[s.w] & smask[d.w]) atomicAdd(&sdeg[d.w], 1);
    }
    __syncthreads();

    // dis = rsqrt(deg + self)
    for (int i = t; i < NN; i += 512) {
        float dg = (float)sdeg[i] + (float)smask[i];
        sdis[i] = (dg > 0.f) ? rsqrtf(dg) : 0.f;
        g_dis[mb + i] = sdis[i];
    }
    __syncthreads();

    // exclusive scan of sdeg -> srow (each thread owns 4 consecutive entries)
    {
        int base = t * 4;
        int a0 = sdeg[base], a1 = sdeg[base + 1], a2 = sdeg[base + 2], a3 = sdeg[base + 3];
        int tot = a0 + a1 + a2 + a3;
        ssum[t] = tot;
        __syncthreads();
#pragma unroll
        for (int off = 1; off < 512; off <<= 1) {
            int v = ssum[t];
            int u = (t >= off) ? ssum[t - off] : 0;
            __syncthreads();
            ssum[t] = v + u;
            __syncthreads();
        }
        int excl = ssum[t] - tot;
        srow[base]     = excl;
        srow[base + 1] = excl + a0;
        srow[base + 2] = excl + a0 + a1;
        srow[base + 3] = excl + a0 + a1 + a2;
        scur[base]     = srow[base];
        scur[base + 1] = srow[base + 1];
        scur[base + 2] = srow[base + 2];
        scur[base + 3] = srow[base + 3];
    }
    __syncthreads();

    // write rowptr
    int* rp = g_rowptr + (size_t)b * (NN + 1);
    for (int i = t; i < NN; i += 512) rp[i] = srow[i];
    if (t == 511) {
        rp[NN] = ssum[511];
        g_n[b] = s_n;
    }
    __syncthreads();

    // scatter valid edges with norm
    float2* csr = g_csr + (size_t)b * EE;
    for (int e4 = t; e4 < EE / 4; e4 += 512) {
        int4 s = src4[e4], d = dst4[e4];
        int ss[4] = {s.x, s.y, s.z, s.w};
        int dd[4] = {d.x, d.y, d.z, d.w};
#pragma unroll
        for (int k = 0; k < 4; k++) {
            if (smask[ss[k]] & smask[dd[k]]) {
                int pos = atomicAdd(&scur[dd[k]], 1);
                float2 v;
                v.x = __int_as_float(ss[k]);
                v.y = sdis[ss[k]] * sdis[dd[k]];
                csr[pos] = v;
            }
        }
    }
}

// ---------------------------------------------------------------------------
// K1: fused GCN layer. One CTA per (batch, 128-node tile), 256 threads.
//   Early exit: node_mask is a prefix (arange < n), so tiles fully beyond n
//   produce zeros that nothing downstream reads -> skip whole CTA.
//   Phase 1: CSR gather-aggregate z rows into smem (no atomics).
//   Phase 2: 128xF @ Fx64 GEMM from smem + bias + mask + relu.
//   Epilogue: F==32 -> write h1 to gmem;  F==64 -> accumulate pooled sums.
// ---------------------------------------------------------------------------
template <int F>
__global__ __launch_bounds__(256) void k_layer(const float* __restrict__ xin,
                                               const float* __restrict__ W,
                                               const float* __restrict__ bias,
                                               const unsigned char* __restrict__ msk) {
    constexpr int SZ = F + 4;  // padded row stride (multiple of 4 for float4)
    extern __shared__ float sm[];
    float* sz = sm;              // 128 * SZ
    float* sW = sz + 128 * SZ;   // F * 64
    float* sb = sW + F * 64;     // 64
    float* sp = sb + 64;         // 64 (layer-2 pool partials)

    const int t = threadIdx.x;
    const int b = blockIdx.x >> 4;               // 16 tiles per batch
    const size_t gnode0 = (size_t)blockIdx.x * 128;
    const int lnode0 = (blockIdx.x & 15) * 128;  // first node within batch

    // ---- prefix-mask early exit: tile entirely beyond valid nodes ----
    // h1 rows >= n are never read (edges endpoint-validated; self term has
    // dis=0 and stale g_h contents are always finite), and pool contribution
    // of masked rows is zero. Skip the whole CTA.
    if (lnode0 >= g_n[b]) return;

    for (int i = t; i < F * 64; i += 256) sW[i] = W[i];
    if (t < 64) {
        sb[t] = bias[t];
        if (F == 64) sp[t] = 0.f;
    }

    const float* hb = (F == 32) ? xin + (size_t)b * NN * 32
                                : (const float*)g_h + (size_t)b * NN * 64;
    const float2* csr = g_csr + (size_t)b * EE;
    const int* rp = g_rowptr + (size_t)b * (NN + 1);
    const float* dis = g_dis + (size_t)b * NN;

    const int warp = t >> 5, lane = t & 31;

    // ---- Phase 1: gather-aggregate ----
    if (F == 64) {
        const int g = lane >> 4, cl = lane & 15;  // 2 groups x 16 lanes x float4
#pragma unroll 1
        for (int k = 0; k < 16; k++) {
            const int li = warp * 16 + k;
            const int i = lnode0 + li;
            const int r0 = rp[i], r1 = rp[i + 1];
            float4 acc = make_float4(0.f, 0.f, 0.f, 0.f);
            if (g == 0) {
                float di = dis[i];
                float s = di * di;
                float4 hv = *(const float4*)(hb + (size_t)i * 64 + cl * 4);
                acc.x = s * hv.x; acc.y = s * hv.y; acc.z = s * hv.z; acc.w = s * hv.w;
            }
            for (int e = r0 + g; e < r1; e += 2) {
                float2 c = csr[e];
                const float4 gv = *(const float4*)(hb + (size_t)__float_as_int(c.x) * 64 + cl * 4);
                acc.x = fmaf(c.y, gv.x, acc.x);
                acc.y = fmaf(c.y, gv.y, acc.y);
                acc.z = fmaf(c.y, gv.z, acc.z);
                acc.w = fmaf(c.y, gv.w, acc.w);
            }
            acc.x += __shfl_xor_sync(0xffffffffu, acc.x, 16);
            acc.y += __shfl_xor_sync(0xffffffffu, acc.y, 16);
            acc.z += __shfl_xor_sync(0xffffffffu, acc.z, 16);
            acc.w += __shfl_xor_sync(0xffffffffu, acc.w, 16);
            if (g == 0) *(float4*)(sz + li * SZ + cl * 4) = acc;
        }
    } else {
        const int g = lane >> 3, cl = lane & 7;  // 4 groups x 8 lanes x float4
#pragma unroll 1
        for (int k = 0; k < 16; k++) {
            const int li = warp * 16 + k;
            const int i = lnode0 + li;
            const int r0 = rp[i], r1 = rp[i + 1];
            float4 acc = make_float4(0.f, 0.f, 0.f, 0.f);
            if (g == 0) {
                float di = dis[i];
                float s = di * di;
                float4 hv = *(const float4*)(hb + (size_t)i * 32 + cl * 4);
                acc.x = s * hv.x; acc.y = s * hv.y; acc.z = s * hv.z; acc.w = s * hv.w;
            }
            for (int e = r0 + g; e < r1; e += 4) {
                float2 c = csr[e];
                const float4 gv = *(const float4*)(hb + (size_t)__float_as_int(c.x) * 32 + cl * 4);
                acc.x = fmaf(c.y, gv.x, acc.x);
                acc.y = fmaf(c.y, gv.y, acc.y);
                acc.z = fmaf(c.y, gv.z, acc.z);
                acc.w = fmaf(c.y, gv.w, acc.w);
            }
            acc.x += __shfl_xor_sync(0xffffffffu, acc.x, 8);
            acc.y += __shfl_xor_sync(0xffffffffu, acc.y, 8);
            acc.z += __shfl_xor_sync(0xffffffffu, acc.z, 8);
            acc.w += __shfl_xor_sync(0xffffffffu, acc.w, 8);
            acc.x += __shfl_xor_sync(0xffffffffu, acc.x, 16);
            acc.y += __shfl_xor_sync(0xffffffffu, acc.y, 16);
            acc.z += __shfl_xor_sync(0xffffffffu, acc.z, 16);
            acc.w += __shfl_xor_sync(0xffffffffu, acc.w, 16);
            if (g == 0) *(float4*)(sz + li * SZ + cl * 4) = acc;
        }
    }
    __syncthreads();

    // ---- Phase 2: GEMM (each thread: 2 nodes x 16 channels) ----
    const int cg = t & 3;     // channel group (16 ch)
    const int ng = t >> 2;    // node slot 0..63 (rows ng and ng+64)
    const bool wide = mask_is_wide(msk);

    float acc[2][16];
#pragma unroll
    for (int k = 0; k < 2; k++)
#pragma unroll
        for (int j = 0; j < 16; j++) acc[k][j] = 0.f;

    for (int f = 0; f < F; f += 4) {
        float4 z0 = *(const float4*)(sz + ng * SZ + f);
        float4 z1 = *(const float4*)(sz + (ng + 64) * SZ + f);
        float zr0[4] = {z0.x, z0.y, z0.z, z0.w};
        float zr1[4] = {z1.x, z1.y, z1.z, z1.w};
#pragma unroll
        for (int ff = 0; ff < 4; ff++) {
            float wv[16];
            const float4* wr = (const float4*)(sW + (f + ff) * 64 + cg * 16);
            *(float4*)&wv[0]  = wr[0];
            *(float4*)&wv[4]  = wr[1];
            *(float4*)&wv[8]  = wr[2];
            *(float4*)&wv[12] = wr[3];
#pragma unroll
            for (int j = 0; j < 16; j++) {
                acc[0][j] = fmaf(zr0[ff], wv[j], acc[0][j]);
                acc[1][j] = fmaf(zr1[ff], wv[j], acc[1][j]);
            }
        }
    }

    // ---- Epilogue ----
    if (F == 32) {
        // layer 1: h1 = relu((z@W1 + b1) * mask) -> gmem
#pragma unroll
        for (int k = 0; k < 2; k++) {
            size_t gn = gnode0 + ng + 64 * k;
            float m = mask_at(msk, wide, gn) ? 1.f : 0.f;
            float* outp = g_h + gn * 64 + cg * 16;
#pragma unroll
            for (int q = 0; q < 4; q++) {
                float4 o;
                o.x = fmaxf((acc[k][q * 4 + 0] + sb[cg * 16 + q * 4 + 0]) * m, 0.f);
                o.y = fmaxf((acc[k][q * 4 + 1] + sb[cg * 16 + q * 4 + 1]) * m, 0.f);
                o.z = fmaxf((acc[k][q * 4 + 2] + sb[cg * 16 + q * 4 + 2]) * m, 0.f);
                o.w = fmaxf((acc[k][q * 4 + 3] + sb[cg * 16 + q * 4 + 3]) * m, 0.f);
                ((float4*)outp)[q] = o;
            }
        }
    } else {
        // layer 2: h2 feeds only pooling -> accumulate sum over nodes
        float ps[16];
#pragma unroll
        for (int j = 0; j < 16; j++) ps[j] = 0.f;
#pragma unroll
        for (int k = 0; k < 2; k++) {
            size_t gn = gnode0 + ng + 64 * k;
            float m = mask_at(msk, wide, gn) ? 1.f : 0.f;
#pragma unroll
            for (int j = 0; j < 16; j++)
                ps[j] += fmaxf((acc[k][j] + sb[cg * 16 + j]) * m, 0.f);
        }
        // butterfly over node-group lanes (bits 2..4) — all lanes share cg
#pragma unroll
        for (int j = 0; j < 16; j++) {
            float v = ps[j];
            v += __shfl_xor_sync(0xffffffffu, v, 4);
            v += __shfl_xor_sync(0xffffffffu, v, 8);
            v += __shfl_xor_sync(0xffffffffu, v, 16);
            ps[j] = v;
        }
        if (lane < 4) {  // lane == cg for these lanes
#pragma unroll
            for (int j = 0; j < 16; j++) atomicAdd(&sp[lane * 16 + j], ps[j]);
        }
        __syncthreads();
        if (t < 64) atomicAdd(&g_pool[b * 64 + t], sp[t]);
    }
}

// ---------------------------------------------------------------------------
// K2: finish pooling (divide by n) + 2-layer MLP head, one CTA per batch
// ---------------------------------------------------------------------------
__global__ __launch_bounds__(64) void k_pool(const float* __restrict__ aW1,
                                             const float* __restrict__ ab1,
                                             const float* __restrict__ aW2,
                                             const float* __restrict__ ab2,
                                             float* __restrict__ out) {
    __shared__ float pooled[64];
    __shared__ float hid[64];
    const int b = blockIdx.x, t = threadIdx.x;
    int n = g_n[b];
    if (n < 1) n = 1;
    pooled[t] = g_pool[b * 64 + t] / (float)n;
    __syncthreads();
    {
        float a = ab1[t];
#pragma unroll
        for (int f = 0; f < 64; f++) a = fmaf(pooled[f], aW1[f * 64 + t], a);
        hid[t] = fmaxf(a, 0.f);
    }
    __syncthreads();
    if (t < 16) {
        float a = ab2[t];
#pragma unroll
        for (int f = 0; f < 64; f++) a = fmaf(hid[f], aW2[f * 16 + t], a);
        out[b * 16 + t] = a;
    }
}

// ---------------------------------------------------------------------------
extern "C" void kernel_launch(void* const* d_in, const int* in_sizes, int n_in,
                              void* d_out, int out_size) {
    const float*         x   = (const float*)d_in[0];
    const int*           ei  = (const int*)d_in[1];
    const unsigned char* msk = (const unsigned char*)d_in[2];
    const float* W1  = (const float*)d_in[3];
    const float* b1  = (const float*)d_in[4];
    const float* W2  = (const float*)d_in[5];
    const float* b2  = (const float*)d_in[6];
    const float* aW1 = (const float*)d_in[7];
    const float* ab1 = (const float*)d_in[8];
    const float* aW2 = (const float*)d_in[9];
    const float* ab2 = (const float*)d_in[10];
    float* out = (float*)d_out;

    const int sm32 = (128 * 36 + 32 * 64 + 64 + 64) * 4;  // ~26.5 KB
    const int sm64 = (128 * 68 + 64 * 64 + 64 + 64) * 4;  // ~50.5 KB
    cudaFuncSetAttribute(k_layer<32>, cudaFuncAttributeMaxDynamicSharedMemorySize, sm32);
    cudaFuncSetAttribute(k_layer<64>, cudaFuncAttributeMaxDynamicSharedMemorySize, sm64);

    // prep: degrees, dis, CSR with per-edge norm (invalid edges dropped), zero pools
    k_prep<<<BB, 512>>>(ei, msk);
    // layer 1 fused: gather(x) -> GEMM(W1) -> h1
    k_layer<32><<<(BB * NN) / 128, 256, sm32>>>(x, W1, b1, msk);
    // layer 2 fused: gather(h1) -> GEMM(W2) -> pooled partial sums
    k_layer<64><<<(BB * NN) / 128, 256, sm64>>>(x, W2, b2, msk);
    // finish pool + MLP head
    k_pool<<<BB, 64>>>(aW1, ab1, aW2, ab2, out);
}

// round 13
// speedup vs baseline: 1.9253x; 1.0092x over previous
#include <cuda_runtime.h>
#include <stdint.h>
#include <stddef.h>

#define BB 128
#define NN 2048
#define EE 16384

// scratch (static device globals; no runtime allocation)
__device__ float  g_dis[BB * NN];
__device__ int    g_n[BB];
__device__ int    g_rowptr[BB * (NN + 1)];
__device__ float2 g_csr[(size_t)BB * EE];     // .x = src (int bits), .y = norm
__device__ float  g_h[(size_t)BB * NN * 64];  // h1 (layer-1 output)
__device__ float  g_pool[BB * 64];            // pooled partial sums

typedef unsigned long long ull;

__device__ __forceinline__ void fma2(ull& d, ull a, ull b) {
    asm("fma.rn.f32x2 %0, %1, %2, %0;" : "+l"(d) : "l"(a), "l"(b));
}
__device__ __forceinline__ ull pack2(float x, float y) {
    ull r; asm("mov.b64 %0, {%1, %2};" : "=l"(r) : "f"(x), "f"(y)); return r;
}
__device__ __forceinline__ float2 unpack2(ull v) {
    float2 u; asm("mov.b64 {%0, %1}, %2;" : "=f"(u.x), "=f"(u.y) : "l"(v)); return u;
}

// node_mask dtype hedge: rows are prefix masks with n >= 1024, so element 1 is
// always "true". If stored as 1-byte bool, byte[1]==1. If stored as int32 or
// float32 (4-byte elems), byte[1]==0.
__device__ __forceinline__ bool mask_is_wide(const unsigned char* m) {
    return m[1] == 0;
}
__device__ __forceinline__ bool mask_at(const unsigned char* m, bool wide, size_t idx) {
    return wide ? (((const int*)m)[idx] != 0) : (m[idx] != 0);
}

// ---------------------------------------------------------------------------
// K0: per-batch degree, dis = rsqrt(deg), CSR build (valid edges only, with
// per-edge norm precomputed), node count n, zero pool accumulators.
// One 512-thread CTA per batch. Edge lists read as int4.
// ---------------------------------------------------------------------------
__global__ __launch_bounds__(512) void k_prep(const int* __restrict__ ei,
                                              const unsigned char* __restrict__ msk) {
    __shared__ int   sdeg[NN];
    __shared__ float sdis[NN];
    __shared__ int   srow[NN];
    __shared__ int   scur[NN];
    __shared__ int   ssum[512];
    __shared__ unsigned char smask[NN];
    __shared__ int   s_n;

    const int b = blockIdx.x;
    const int t = threadIdx.x;
    const bool wide = mask_is_wide(msk);
    const size_t mb = (size_t)b * NN;
    const int* src = ei + (size_t)b * 2 * EE;
    const int* dst = src + EE;
    const int4* src4 = (const int4*)src;
    const int4* dst4 = (const int4*)dst;

    if (t == 0) s_n = 0;
    if (t < 64) g_pool[b * 64 + t] = 0.f;
    int cnt = 0;
    for (int i = t; i < NN; i += 512) {
        sdeg[i] = 0;
        unsigned char m = mask_at(msk, wide, mb + i) ? 1 : 0;
        smask[i] = m;
        cnt += m;
    }
    __syncthreads();
    atomicAdd(&s_n, cnt);

    // degree of valid edges (4 edges per thread-iter)
    for (int e4 = t; e4 < EE / 4; e4 += 512) {
        int4 s = src4[e4], d = dst4[e4];
        if (smask[s.x] & smask[d.x]) atomicAdd(&sdeg[d.x], 1);
        if (smask[s.y] & smask[d.y]) atomicAdd(&sdeg[d.y], 1);
        if (smask[s.z] & smask[d.z]) atomicAdd(&sdeg[d.z], 1);
        if (smask[s.w] & smask[d.w]) atomicAdd(&sdeg[d.w], 1);
    }
    __syncthreads();

    // dis = rsqrt(deg + self)
    for (int i = t; i < NN; i += 512) {
        float dg = (float)sdeg[i] + (float)smask[i];
        sdis[i] = (dg > 0.f) ? rsqrtf(dg) : 0.f;
        g_dis[mb + i] = sdis[i];
    }
    __syncthreads();

    // exclusive scan of sdeg -> srow (each thread owns 4 consecutive entries)
    {
        int base = t * 4;
        int a0 = sdeg[base], a1 = sdeg[base + 1], a2 = sdeg[base + 2], a3 = sdeg[base + 3];
        int tot = a0 + a1 + a2 + a3;
        ssum[t] = tot;
        __syncthreads();
#pragma unroll
        for (int off = 1; off < 512; off <<= 1) {
            int v = ssum[t];
            int u = (t >= off) ? ssum[t - off] : 0;
            __syncthreads();
            ssum[t] = v + u;
            __syncthreads();
        }
        int excl = ssum[t] - tot;
        srow[base]     = excl;
        srow[base + 1] = excl + a0;
        srow[base + 2] = excl + a0 + a1;
        srow[base + 3] = excl + a0 + a1 + a2;
        scur[base]     = srow[base];
        scur[base + 1] = srow[base + 1];
        scur[base + 2] = srow[base + 2];
        scur[base + 3] = srow[base + 3];
    }
    __syncthreads();

    // write rowptr
    int* rp = g_rowptr + (size_t)b * (NN + 1);
    for (int i = t; i < NN; i += 512) rp[i] = srow[i];
    if (t == 511) {
        rp[NN] = ssum[511];
        g_n[b] = s_n;
    }
    __syncthreads();

    // scatter valid edges with norm
    float2* csr = g_csr + (size_t)b * EE;
    for (int e4 = t; e4 < EE / 4; e4 += 512) {
        int4 s = src4[e4], d = dst4[e4];
        int ss[4] = {s.x, s.y, s.z, s.w};
        int dd[4] = {d.x, d.y, d.z, d.w};
#pragma unroll
        for (int k = 0; k < 4; k++) {
            if (smask[ss[k]] & smask[dd[k]]) {
                int pos = atomicAdd(&scur[dd[k]], 1);
                float2 v;
                v.x = __int_as_float(ss[k]);
                v.y = sdis[ss[k]] * sdis[dd[k]];
                csr[pos] = v;
            }
        }
    }
}

// ---------------------------------------------------------------------------
// K1: fused GCN layer. One CTA per (batch, 128-node tile), 256 threads.
//   Early exit: node_mask is a prefix (arange < n), so tiles fully beyond n
//   produce zeros that nothing downstream reads -> skip whole CTA.
//   Phase 1: CSR gather-aggregate z rows into smem (no atomics).
//   Phase 2: 128xF @ Fx64 GEMM from smem via packed fma.rn.f32x2.
//   Epilogue: F==32 -> write h1 to gmem;  F==64 -> accumulate pooled sums.
// ---------------------------------------------------------------------------
template <int F>
__global__ __launch_bounds__(256) void k_layer(const float* __restrict__ xin,
                                               const float* __restrict__ W,
                                               const float* __restrict__ bias,
                                               const unsigned char* __restrict__ msk) {
    constexpr int SZ = F + 4;  // padded row stride (multiple of 4 for float4)
    extern __shared__ float sm[];
    float* sz = sm;              // 128 * SZ
    float* sW = sz + 128 * SZ;   // F * 64
    float* sb = sW + F * 64;     // 64
    float* sp = sb + 64;         // 64 (layer-2 pool partials)

    const int t = threadIdx.x;
    const int b = blockIdx.x >> 4;               // 16 tiles per batch
    const size_t gnode0 = (size_t)blockIdx.x * 128;
    const int lnode0 = (blockIdx.x & 15) * 128;  // first node within batch

    // ---- prefix-mask early exit: tile entirely beyond valid nodes ----
    if (lnode0 >= g_n[b]) return;

    for (int i = t; i < F * 64; i += 256) sW[i] = W[i];
    if (t < 64) {
        sb[t] = bias[t];
        if (F == 64) sp[t] = 0.f;
    }

    const float* hb = (F == 32) ? xin + (size_t)b * NN * 32
                                : (const float*)g_h + (size_t)b * NN * 64;
    const float2* csr = g_csr + (size_t)b * EE;
    const int* rp = g_rowptr + (size_t)b * (NN + 1);
    const float* dis = g_dis + (size_t)b * NN;

    const int warp = t >> 5, lane = t & 31;

    // ---- Phase 1: gather-aggregate ----
    if (F == 64) {
        const int g = lane >> 4, cl = lane & 15;  // 2 groups x 16 lanes x float4
#pragma unroll 1
        for (int k = 0; k < 16; k++) {
            const int li = warp * 16 + k;
            const int i = lnode0 + li;
            const int r0 = rp[i], r1 = rp[i + 1];
            float4 acc = make_float4(0.f, 0.f, 0.f, 0.f);
            if (g == 0) {
                float di = dis[i];
                float s = di * di;
                float4 hv = *(const float4*)(hb + (size_t)i * 64 + cl * 4);
                acc.x = s * hv.x; acc.y = s * hv.y; acc.z = s * hv.z; acc.w = s * hv.w;
            }
            for (int e = r0 + g; e < r1; e += 2) {
                float2 c = csr[e];
                const float4 gv = *(const float4*)(hb + (size_t)__float_as_int(c.x) * 64 + cl * 4);
                acc.x = fmaf(c.y, gv.x, acc.x);
                acc.y = fmaf(c.y, gv.y, acc.y);
                acc.z = fmaf(c.y, gv.z, acc.z);
                acc.w = fmaf(c.y, gv.w, acc.w);
            }
            acc.x += __shfl_xor_sync(0xffffffffu, acc.x, 16);
            acc.y += __shfl_xor_sync(0xffffffffu, acc.y, 16);
            acc.z += __shfl_xor_sync(0xffffffffu, acc.z, 16);
            acc.w += __shfl_xor_sync(0xffffffffu, acc.w, 16);
            if (g == 0) *(float4*)(sz + li * SZ + cl * 4) = acc;
        }
    } else {
        const int g = lane >> 3, cl = lane & 7;  // 4 groups x 8 lanes x float4
#pragma unroll 1
        for (int k = 0; k < 16; k++) {
            const int li = warp * 16 + k;
            const int i = lnode0 + li;
            const int r0 = rp[i], r1 = rp[i + 1];
            float4 acc = make_float4(0.f, 0.f, 0.f, 0.f);
            if (g == 0) {
                float di = dis[i];
                float s = di * di;
                float4 hv = *(const float4*)(hb + (size_t)i * 32 + cl * 4);
                acc.x = s * hv.x; acc.y = s * hv.y; acc.z = s * hv.z; acc.w = s * hv.w;
            }
            for (int e = r0 + g; e < r1; e += 4) {
                float2 c = csr[e];
                const float4 gv = *(const float4*)(hb + (size_t)__float_as_int(c.x) * 32 + cl * 4);
                acc.x = fmaf(c.y, gv.x, acc.x);
                acc.y = fmaf(c.y, gv.y, acc.y);
                acc.z = fmaf(c.y, gv.z, acc.z);
                acc.w = fmaf(c.y, gv.w, acc.w);
            }
            acc.x += __shfl_xor_sync(0xffffffffu, acc.x, 8);
            acc.y += __shfl_xor_sync(0xffffffffu, acc.y, 8);
            acc.z += __shfl_xor_sync(0xffffffffu, acc.z, 8);
            acc.w += __shfl_xor_sync(0xffffffffu, acc.w, 8);
            acc.x += __shfl_xor_sync(0xffffffffu, acc.x, 16);
            acc.y += __shfl_xor_sync(0xffffffffu, acc.y, 16);
            acc.z += __shfl_xor_sync(0xffffffffu, acc.z, 16);
            acc.w += __shfl_xor_sync(0xffffffffu, acc.w, 16);
            if (g == 0) *(float4*)(sz + li * SZ + cl * 4) = acc;
        }
    }
    __syncthreads();

    // ---- Phase 2: GEMM via packed fma.rn.f32x2 (2 nodes x 16 channels/thread) ----
    const int cg = t & 3;     // channel group (16 ch = 8 packed pairs)
    const int ng = t >> 2;    // node slot 0..63 (rows ng and ng+64)
    const bool wide = mask_is_wide(msk);

    ull acc0[8], acc1[8];
#pragma unroll
    for (int j = 0; j < 8; j++) { acc0[j] = 0ull; acc1[j] = 0ull; }

    const float* zr0p = sz + ng * SZ;
    const float* zr1p = sz + (ng + 64) * SZ;
#pragma unroll
    for (int f = 0; f < F; f += 4) {
        float4 z0 = *(const float4*)(zr0p + f);
        float4 z1 = *(const float4*)(zr1p + f);
        float za0[4] = {z0.x, z0.y, z0.z, z0.w};
        float za1[4] = {z1.x, z1.y, z1.z, z1.w};
#pragma unroll
        for (int ff = 0; ff < 4; ff++) {
            ull zp0 = pack2(za0[ff], za0[ff]);
            ull zp1 = pack2(za1[ff], za1[ff]);
            const ulonglong2* wp = (const ulonglong2*)(sW + (f + ff) * 64 + cg * 16);
            ulonglong2 wA = wp[0], wB = wp[1], wC = wp[2], wD = wp[3];
            fma2(acc0[0], zp0, wA.x); fma2(acc0[1], zp0, wA.y);
            fma2(acc0[2], zp0, wB.x); fma2(acc0[3], zp0, wB.y);
            fma2(acc0[4], zp0, wC.x); fma2(acc0[5], zp0, wC.y);
            fma2(acc0[6], zp0, wD.x); fma2(acc0[7], zp0, wD.y);
            fma2(acc1[0], zp1, wA.x); fma2(acc1[1], zp1, wA.y);
            fma2(acc1[2], zp1, wB.x); fma2(acc1[3], zp1, wB.y);
            fma2(acc1[4], zp1, wC.x); fma2(acc1[5], zp1, wC.y);
            fma2(acc1[6], zp1, wD.x); fma2(acc1[7], zp1, wD.y);
        }
    }

    // unpack accumulators to scalar channel values
    float oa[2][16];
#pragma unroll
    for (int j = 0; j < 8; j++) {
        float2 u0 = unpack2(acc0[j]);
        float2 u1 = unpack2(acc1[j]);
        oa[0][2 * j] = u0.x; oa[0][2 * j + 1] = u0.y;
        oa[1][2 * j] = u1.x; oa[1][2 * j + 1] = u1.y;
    }

    // ---- Epilogue ----
    if (F == 32) {
        // layer 1: h1 = relu((z@W1 + b1) * mask) -> gmem
#pragma unroll
        for (int k = 0; k < 2; k++) {
            size_t gn = gnode0 + ng + 64 * k;
            float m = mask_at(msk, wide, gn) ? 1.f : 0.f;
            float* outp = g_h + gn * 64 + cg * 16;
#pragma unroll
            for (int q = 0; q < 4; q++) {
                float4 o;
                o.x = fmaxf((oa[k][q * 4 + 0] + sb[cg * 16 + q * 4 + 0]) * m, 0.f);
                o.y = fmaxf((oa[k][q * 4 + 1] + sb[cg * 16 + q * 4 + 1]) * m, 0.f);
                o.z = fmaxf((oa[k][q * 4 + 2] + sb[cg * 16 + q * 4 + 2]) * m, 0.f);
                o.w = fmaxf((oa[k][q * 4 + 3] + sb[cg * 16 + q * 4 + 3]) * m, 0.f);
                ((float4*)outp)[q] = o;
            }
        }
    } else {
        // layer 2: h2 feeds only pooling -> accumulate sum over nodes
        float ps[16];
#pragma unroll
        for (int j = 0; j < 16; j++) ps[j] = 0.f;
#pragma unroll
        for (int k = 0; k < 2; k++) {
            size_t gn = gnode0 + ng + 64 * k;
            float m = mask_at(msk, wide, gn) ? 1.f : 0.f;
#pragma unroll
            for (int j = 0; j < 16; j++)
                ps[j] += fmaxf((oa[k][j] + sb[cg * 16 + j]) * m, 0.f);
        }
        // butterfly over node-group lanes (bits 2..4) — all lanes share cg
#pragma unroll
        for (int j = 0; j < 16; j++) {
            float v = ps[j];
            v += __shfl_xor_sync(0xffffffffu, v, 4);
            v += __shfl_xor_sync(0xffffffffu, v, 8);
            v += __shfl_xor_sync(0xffffffffu, v, 16);
            ps[j] = v;
        }
        if (lane < 4) {  // lane == cg for these lanes
#pragma unroll
            for (int j = 0; j < 16; j++) atomicAdd(&sp[lane * 16 + j], ps[j]);
        }
        __syncthreads();
        if (t < 64) atomicAdd(&g_pool[b * 64 + t], sp[t]);
    }
}

// ---------------------------------------------------------------------------
// K2: finish pooling (divide by n) + 2-layer MLP head, one CTA per batch
// ---------------------------------------------------------------------------
__global__ __launch_bounds__(64) void k_pool(const float* __restrict__ aW1,
                                             const float* __restrict__ ab1,
                                             const float* __restrict__ aW2,
                                             const float* __restrict__ ab2,
                                             float* __restrict__ out) {
    __shared__ float pooled[64];
    __shared__ float hid[64];
    const int b = blockIdx.x, t = threadIdx.x;
    int n = g_n[b];
    if (n < 1) n = 1;
    pooled[t] = g_pool[b * 64 + t] / (float)n;
    __syncthreads();
    {
        float a = ab1[t];
#pragma unroll
        for (int f = 0; f < 64; f++) a = fmaf(pooled[f], aW1[f * 64 + t], a);
        hid[t] = fmaxf(a, 0.f);
    }
    __syncthreads();
    if (t < 16) {
        float a = ab2[t];
#pragma unroll
        for (int f = 0; f < 64; f++) a = fmaf(hid[f], aW2[f * 16 + t], a);
        out[b * 16 + t] = a;
    }
}

// ---------------------------------------------------------------------------
extern "C" void kernel_launch(void* const* d_in, const int* in_sizes, int n_in,
                              void* d_out, int out_size) {
    const float*         x   = (const float*)d_in[0];
    const int*           ei  = (const int*)d_in[1];
    const unsigned char* msk = (const unsigned char*)d_in[2];
    const float* W1  = (const float*)d_in[3];
    const float* b1  = (const float*)d_in[4];
    const float* W2  = (const float*)d_in[5];
    const float* b2  = (const float*)d_in[6];
    const float* aW1 = (const float*)d_in[7];
    const float* ab1 = (const float*)d_in[8];
    const float* aW2 = (const float*)d_in[9];
    const float* ab2 = (const float*)d_in[10];
    float* out = (float*)d_out;

    const int sm32 = (128 * 36 + 32 * 64 + 64 + 64) * 4;  // ~26.5 KB
    const int sm64 = (128 * 68 + 64 * 64 + 64 + 64) * 4;  // ~50.5 KB
    cudaFuncSetAttribute(k_layer<32>, cudaFuncAttributeMaxDynamicSharedMemorySize, sm32);
    cudaFuncSetAttribute(k_layer<64>, cudaFuncAttributeMaxDynamicSharedMemorySize, sm64);

    // prep: degrees, dis, CSR with per-edge norm (invalid edges dropped), zero pools
    k_prep<<<BB, 512>>>(ei, msk);
    // layer 1 fused: gather(x) -> GEMM(W1) -> h1
    k_layer<32><<<(BB * NN) / 128, 256, sm32>>>(x, W1, b1, msk);
    // layer 2 fused: gather(h1) -> GEMM(W2) -> pooled partial sums
    k_layer<64><<<(BB * NN) / 128, 256, sm64>>>(x, W2, b2, msk);
    // finish pool + MLP head
    k_pool<<<BB, 64>>>(aW1, ab1, aW2, ab2, out);
}